// round 1
// baseline (speedup 1.0000x reference)
#include <cuda_runtime.h>
#include <math.h>
#include <stdint.h>

#define NSAMP  8
#define NEXP   256
#define NMARK  10
#define KBOUND 40

// softplus(x) = max(x,0) + log1p(exp(-|x|)); fast MUFU path (EX2 + LG2)
__device__ __forceinline__ float softplus_f(float x) {
    float z = __expf(-fabsf(x));
    return fmaxf(x, 0.0f) + __logf(1.0f + z);
}

// cos with explicit Cody-Waite reduction by 2*pi (t up to ~350, k <= ~60),
// then MUFU cos on r in [-pi, pi]. Angle error ~2.5e-7, cos error ~6e-7,
// flag-agnostic (explicit intrinsics behave the same with/without fast-math).
__device__ __forceinline__ float cos_cw(float t) {
    const float INV2PI   = 0.15915494309189535f;
    const float TWOPI_HI = 6.2831854820251465f;   // float(2*pi)
    const float TWOPI_LO = -1.7484555e-07f;       // 2*pi - TWOPI_HI
    float k = rintf(t * INV2PI);
    float r = fmaf(-k, TWOPI_HI, t);
    r = fmaf(-k, TWOPI_LO, r);
    return __cosf(r);
}

__global__ void __launch_bounds__(256) sampler_kernel(
    const float* __restrict__ time_seq,
    const float* __restrict__ dt_seq,
    const int*   __restrict__ ev_w,     // raw 32-bit words of event_seq (int32 or int64)
    const float* __restrict__ exp_raw,
    const float* __restrict__ unif,
    const float* __restrict__ emb,
    const float* __restrict__ scale,
    const float* __restrict__ bias,
    float* __restrict__ out_res,
    float* __restrict__ out_w,
    int write_w)
{
    const int row  = blockIdx.x;
    const int tid  = threadIdx.x;
    const int lane = tid & 31;
    const int warp = tid >> 5;

    __shared__ float s_c0[NMARK];
    __shared__ float s_sc[NMARK];
    __shared__ float s_red[8 * NSAMP];
    __shared__ float s_upper;

    // ---- issue the big global loads immediately (overlap with boundary phase) ----
    const float exr = exp_raw[(size_t)row * NEXP + tid];
    const float* uptr = unif + (size_t)row * (NSAMP * NEXP) + tid;
    float u[NSAMP];
#pragma unroll
    for (int j = 0; j < NSAMP; j++) u[j] = uptr[(size_t)j * NEXP];

    const float t0  = time_seq[row];
    const float dtv = dt_seq[row];

    if (tid < NMARK) {
        // detect int64 vs int32 encoding of event_seq: for little-endian int64
        // with values in [0,20), every odd 32-bit word is zero.
        int acc = 0;
#pragma unroll
        for (int i = 0; i < 16; i++) acc |= ev_w[2 * i + 1];
        int ev = (acc == 0) ? ev_w[2 * row] : ev_w[row];
        s_c0[tid] = emb[ev * NMARK + tid] + bias[tid];
        s_sc[tid] = scale[tid];
    }
    __syncthreads();

    float c0r[NMARK], scr[NMARK];
#pragma unroll
    for (int m = 0; m < NMARK; m++) { c0r[m] = s_c0[m]; scr[m] = s_sc[m]; }

    // ---- intensity upper bound: max over 40 boundary samples ----
    float lam = -INFINITY;
    if (tid < KBOUND) {
        float t = fmaf(dtv, (float)tid * (1.0f / 39.0f), t0);
        float c = cos_cw(t);
        float ssum = 0.0f;
#pragma unroll
        for (int m = 0; m < NMARK; m++) ssum += softplus_f(fmaf(scr[m], c, c0r[m]));
        lam = ssum;
    }
#pragma unroll
    for (int o = 16; o; o >>= 1)
        lam = fmaxf(lam, __shfl_xor_sync(0xffffffffu, lam, o));
    if (lane == 0) s_red[warp] = lam;
    __syncthreads();
    if (tid == 0) {
        float m = s_red[0];
#pragma unroll
        for (int w2 = 1; w2 < 8; w2++) m = fmaxf(m, s_red[w2]);
        s_upper = 1.5f * m;   // OVER_SAMPLE_RATE
    }
    __syncthreads();
    const float upper = s_upper;

    // ---- per-candidate total intensity + accept test ----
    const float ex = exr / upper;           // exp_numbers
    const float c  = cos_cw(t0 + ex);
    float total = 0.0f;
#pragma unroll
    for (int m = 0; m < NMARK; m++) total += softplus_f(fmaf(scr[m], c, c0r[m]));

    float cand[NSAMP];
#pragma unroll
    for (int j = 0; j < NSAMP; j++)
        cand[j] = (u[j] * upper < total) ? ex : INFINITY;   // accept => candidate dt

    // ---- 8 parallel min-reductions over the 256 candidates ----
#pragma unroll
    for (int j = 0; j < NSAMP; j++) {
#pragma unroll
        for (int o = 16; o; o >>= 1)
            cand[j] = fminf(cand[j], __shfl_xor_sync(0xffffffffu, cand[j], o));
    }
    if (lane == 0) {
#pragma unroll
        for (int j = 0; j < NSAMP; j++) s_red[warp * NSAMP + j] = cand[j];
    }
    __syncthreads();
    if (tid < NSAMP) {
        float m = s_red[tid];
#pragma unroll
        for (int w2 = 1; w2 < 8; w2++) m = fminf(m, s_red[w2 * NSAMP + tid]);
        float r = (m > 1e30f) ? 5.0f : m;   // DTIME_MAX when nothing accepted
        r = fminf(r, 1e5f);
        out_res[row * NSAMP + tid] = r;
        if (write_w) out_w[row * NSAMP + tid] = 0.125f;  // 1/NUM_SAMPLES
    }
}

extern "C" void kernel_launch(void* const* d_in, const int* in_sizes, int n_in,
                              void* d_out, int out_size) {
    const float* time_seq = (const float*)d_in[0];
    const float* dt_seq   = (const float*)d_in[1];
    const int*   ev_w     = (const int*)  d_in[2];
    const float* exp_raw  = (const float*)d_in[3];
    const float* unif     = (const float*)d_in[4];
    const float* emb      = (const float*)d_in[5];
    const float* scale    = (const float*)d_in[6];
    const float* bias     = (const float*)d_in[7];

    const int n_rows    = in_sizes[0];          // B*S = 16384
    const int res_elems = n_rows * NSAMP;
    float* res  = (float*)d_out;
    float* wout = res + res_elems;
    const int write_w = (out_size >= 2 * res_elems) ? 1 : 0;

    sampler_kernel<<<n_rows, 256>>>(time_seq, dt_seq, ev_w, exp_raw, unif,
                                    emb, scale, bias, res, wout, write_w);
}